// round 8
// baseline (speedup 1.0000x reference)
#include <cuda_runtime.h>

#define H      128
#define STEPS  65536
#define NBLK   27

// Cross-stage activations (device globals; no allocation)
__device__ __align__(16) float g_h[3][H];     // finished LSTM hidden per layer
__device__ __align__(16) float g_fc[400];
__device__ __align__(16) float g_l1[512];     // 500 used, padded
// flags: [stage][slot], slot stride 32 ints = 128B (private line per consumer
// block). stages 0-2: LSTM layer done; 3: FC done; 4: L1 done.
// Zero-init at load; reset in-kernel by the final block each launch.
__device__ int g_flag[5][32 * 32];

__device__ __forceinline__ float tanh_fast(float x) {
    float y; asm("tanh.approx.f32 %0, %1;" : "=f"(y) : "f"(x)); return y;
}
__device__ __forceinline__ float sig_fast(float x) {
    return 0.5f * tanh_fast(0.5f * x) + 0.5f;
}
__device__ __forceinline__ float dot4(float4 a, float4 b) {
    return a.x * b.x + a.y * b.y + a.z * b.z + a.w * b.w;
}
__device__ __forceinline__ int ld_acquire(const int* p) {
    int v;
    asm volatile("ld.acquire.gpu.global.b32 %0, [%1];" : "=r"(v) : "l"(p) : "memory");
    return v;
}
__device__ __forceinline__ void red_release(int* p, int v) {
    asm volatile("red.release.gpu.global.add.s32 [%0], %1;" :: "l"(p), "r"(v) : "memory");
}
// Per-warp wait: lane 0 polls with acquire, syncwarp broadcasts the ordering.
__device__ __forceinline__ void warp_wait(int* p, int tgt) {
    if ((threadIdx.x & 31) == 0) {
        while (ld_acquire(p) < tgt) { }
    }
    __syncwarp();
}

__global__ __launch_bounds__(512, 1)
void fused_rnn(const float* __restrict__ inputs,
               const float* __restrict__ W_ih,
               const float* __restrict__ b_ih,
               const float* __restrict__ b_hh,
               const float* __restrict__ W_fc,
               const float* __restrict__ b_fc,
               const float* __restrict__ W_l1,
               const float* __restrict__ b_l1,
               const float* __restrict__ W_l2,
               const float* __restrict__ b_l2,
               float* __restrict__ out)
{
    __shared__ float sgate[96];                  // LSTM gate exchange
    __shared__ __align__(16) float xin[512];     // L2-stage x staging
    const int b = blockIdx.x;
    const int t = threadIdx.x;

    // ============ LSTM: blocks 0-11 (layer = b>>2, 4 blocks/layer) ============
    // Block `sub` owns h-outputs [sub*32, sub*32+32): computes the i, g, o gate
    // rows for those outputs (f is dead: c0=0), applies activations itself, and
    // publishes finished h. 96 rows x 128-dot, TPR=4 -> 384 active threads.
    if (b < 12) {
        const int layer = b >> 2, sub = b & 3;
        const int r = t >> 2, p = t & 3;
        const bool act = r < 96;

        float4 w[8];
        float bias = 0.0f;
        if (act) {
            const int j = sub * 32;
            const int grow = (r < 32) ? j + r
                           : (r < 64) ? 256 + j + (r - 32)
                                      : 384 + j + (r - 64);
            const float4* wr = reinterpret_cast<const float4*>(
                W_ih + ((size_t)layer * 512 + grow) * H) + p * 8;
#pragma unroll
            for (int k = 0; k < 8; ++k) w[k] = wr[k];
            bias = b_ih[layer * 512 + grow] + b_hh[layer * 512 + grow];
        }

        float4 x[8];
        if (layer == 0) {
            if (act) {
                const float4* xs = reinterpret_cast<const float4*>(
                    inputs + (size_t)(STEPS - 1) * H) + p * 8;
#pragma unroll
                for (int k = 0; k < 8; ++k) x[k] = xs[k];
            }
        } else {
            warp_wait(&g_flag[layer - 1][sub * 32], 4);
            if (act) {
                const float4* xs = reinterpret_cast<const float4*>(g_h[layer - 1]) + p * 8;
#pragma unroll
                for (int k = 0; k < 8; ++k) x[k] = xs[k];
            }
        }

        float s0 = 0.0f, s1 = 0.0f;
#pragma unroll
        for (int k = 0; k < 8; k += 2) { s0 += dot4(w[k], x[k]); s1 += dot4(w[k + 1], x[k + 1]); }
        float s = s0 + s1;
        s += __shfl_down_sync(0xFFFFFFFFu, s, 2, 4);
        s += __shfl_down_sync(0xFFFFFFFFu, s, 1, 4);
        if (p == 0 && act) sgate[r] = s + bias;
        __syncthreads();

        if (t < 32) {                            // warp 0: activation + publish
            float ig = sgate[t], gg = sgate[32 + t], og = sgate[64 + t];
            float c  = sig_fast(ig) * tanh_fast(gg);
            g_h[layer][sub * 32 + t] = sig_fast(og) * tanh_fast(c);
            __syncwarp();
            red_release(&g_flag[layer][t * 32], 1);   // fan out to all slots
        }
        return;
    }

    // ============ FC 400x128: blocks 12-15 (100 rows each, TPR=4) ============
    if (b < 16) {
        const int sub = b - 12;
        const int r = t >> 2, p = t & 3;
        const bool act = r < 100;
        const int gr = sub * 100 + r;

        float4 w[8];
        float bias = 0.0f;
        if (act) {
            const float4* wr = reinterpret_cast<const float4*>(
                W_fc + (size_t)gr * H) + p * 8;
#pragma unroll
            for (int k = 0; k < 8; ++k) w[k] = wr[k];
            bias = b_fc[gr];
        }

        warp_wait(&g_flag[2][sub * 32], 4);

        float s = 0.0f;
        if (act) {
            const float4* xs = reinterpret_cast<const float4*>(g_h[2]) + p * 8;
            float s0 = 0.0f, s1 = 0.0f;
#pragma unroll
            for (int k = 0; k < 8; k += 2) { s0 += dot4(w[k], xs[k]); s1 += dot4(w[k + 1], xs[k + 1]); }
            s = s0 + s1;
        }
        s += __shfl_down_sync(0xFFFFFFFFu, s, 2, 4);
        s += __shfl_down_sync(0xFFFFFFFFu, s, 1, 4);
        if (p == 0 && act) g_fc[gr] = s + bias;

        __syncthreads();
        if (t < 32) red_release(&g_flag[3][t * 32], 1);
        return;
    }

    // ============ L1 500x400: blocks 16-25 (50 rows each, TPR=8) ============
    if (b < 26) {
        const int sub = b - 16;
        const int r = t >> 3, p = t & 7;
        const bool act = r < 50;
        const int gr = sub * 50 + r;

        // float4 chunks c = p*13+k, c < 100
        float4 w[13];
        float bias = 0.0f;
        if (act) {
            const float4* wb = reinterpret_cast<const float4*>(W_l1 + (size_t)gr * 400);
#pragma unroll
            for (int k = 0; k < 13; ++k) {
                int c = p * 13 + k;
                if (c < 100) w[k] = wb[c];
            }
            bias = b_l1[gr];
        }

        warp_wait(&g_flag[3][sub * 32], 4);

        float s = 0.0f;
        if (act) {
            const float4* xf = reinterpret_cast<const float4*>(g_fc);
            float s0 = 0.0f, s1 = 0.0f;
#pragma unroll
            for (int k = 0; k < 13; ++k) {
                int c = p * 13 + k;
                if (c < 100) { float4 xv = xf[c]; if (k & 1) s1 += dot4(w[k], xv); else s0 += dot4(w[k], xv); }
            }
            s = s0 + s1;
        }
#pragma unroll
        for (int off = 4; off > 0; off >>= 1)
            s += __shfl_down_sync(0xFFFFFFFFu, s, off, 8);
        if (p == 0 && act) g_l1[gr] = s + bias;

        __syncthreads();
        if (t < 32) red_release(&g_flag[4][t * 32], 1);
        return;
    }

    // ============ L2 63x500: block 26 (TPR=8) + flag reset ============
    {
        const int r = t >> 3, p = t & 7;
        const bool act = r < 63;

        // float4 chunks c = p*16+k, c < 125 (row base = r*2000B, 16B aligned)
        float4 w[16];
        float bias = 0.0f;
        if (act) {
            const float4* wb = reinterpret_cast<const float4*>(W_l2 + (size_t)r * 500);
#pragma unroll
            for (int k = 0; k < 16; ++k) {
                int c = p * 16 + k;
                if (c < 125) w[k] = wb[c];
            }
            bias = b_l2[r];
        }

        warp_wait(&g_flag[4][0], 10);

        // stage x (500 floats) into smem as float4
        if (t < 125)
            reinterpret_cast<float4*>(xin)[t] =
                reinterpret_cast<const float4*>(g_l1)[t];
        __syncthreads();

        float s = 0.0f;
        if (act) {
            const float4* xs = reinterpret_cast<const float4*>(xin);
            float s0 = 0.0f, s1 = 0.0f;
#pragma unroll
            for (int k = 0; k < 16; ++k) {
                int c = p * 16 + k;
                if (c < 125) { float4 xv = xs[c]; if (k & 1) s1 += dot4(w[k], xv); else s0 += dot4(w[k], xv); }
            }
            s = s0 + s1;
        }
#pragma unroll
        for (int off = 4; off > 0; off >>= 1)
            s += __shfl_down_sync(0xFFFFFFFFu, s, off, 8);
        if (p == 0 && act) out[r] = s + bias;

        // Reset all flag slots for the next graph replay. Safe: this block's
        // wait passing implies (transitively) every other wait has passed and
        // every red.release has landed, so no one touches g_flag again.
        __syncthreads();
        if (t < 160)
            *(volatile int*)&g_flag[t >> 5][(t & 31) * 32] = 0;
    }
}

extern "C" void kernel_launch(void* const* d_in, const int* in_sizes, int n_in,
                              void* d_out, int out_size) {
    const float* inputs = (const float*)d_in[0];
    const float* W_ih   = (const float*)d_in[1];
    // d_in[2] = W_hh — dead (h0 = 0)
    const float* b_ih   = (const float*)d_in[3];
    const float* b_hh   = (const float*)d_in[4];
    const float* W_fc   = (const float*)d_in[5];
    const float* b_fc   = (const float*)d_in[6];
    const float* W_l1   = (const float*)d_in[7];
    const float* b_l1   = (const float*)d_in[8];
    const float* W_l2   = (const float*)d_in[9];
    const float* b_l2   = (const float*)d_in[10];
    float* out = (float*)d_out;

    fused_rnn<<<NBLK, 512>>>(inputs, W_ih, b_ih, b_hh,
                             W_fc, b_fc, W_l1, b_l1, W_l2, b_l2, out);
}